// round 6
// baseline (speedup 1.0000x reference)
#include <cuda_runtime.h>
#include <math.h>

typedef unsigned long long ull;

#define TPB 256
#define GRID1 148      // persistent, 1 CTA/SM
#define CH 512         // samples per chunk (2 per thread)
#define XST 9          // staged x row stride (conflict-free scalar LDS)
#define XBUF (CH*XST)  // 4608 floats per buffer

// ---- constant weight layout (float offsets); OUT padded to %4==0 ----
#define OW1  0      // 120x60
#define OW2  7200   // 60x32 (30 real)
#define OW3  9120   // 30x12 (10 real)
#define OW4  9480   // 10x4
#define OW5  9520   // 4x12 (10 real)
#define OW6  9568   // 10x32 (30 real)
#define OW7  9888   // 30x60
#define OW89 11688  // fused (W8@W9): 60x12 (10 real)
#define OW10 12408  // 10x12 (10 real)
#define OB1  12528
#define OB2  12588
#define OB3  12620
#define OB4  12632
#define OB5  12636
#define OB6  12648
#define OB7  12680
#define OB89 12740
#define OB10 12752
#define WTOTAL 12764
#define SMEM_FLOATS (2*XBUF)
#define SMEM_BYTES  (SMEM_FLOATS*4)   // 36,864 B

struct Params { const float* w[10]; const float* b[10]; };

__device__ float g_stats[152];
__device__ float g_gmm[212];
__device__ float g_wpad[WTOTAL];
__constant__ float cW[WTOTAL];       // 51,056 B < 64KB

// ---------- packed f32x2 helpers ----------
__device__ __forceinline__ ull fma2(ull a, ull b, ull c) {
    ull d; asm("fma.rn.f32x2 %0, %1, %2, %3;" : "=l"(d) : "l"(a), "l"(b), "l"(c)); return d;
}
__device__ __forceinline__ ull pack2(float x) {
    ull r; asm("mov.b64 %0, {%1, %1};" : "=l"(r) : "f"(x)); return r;
}
__device__ __forceinline__ void unpack2(float& lo, float& hi, ull v) {
    asm("mov.b64 {%0, %1}, %2;" : "=f"(lo), "=f"(hi) : "l"(v));
}
__device__ __forceinline__ float tanh_fast(float x) {
    float xc = fminf(fmaxf(x, -10.0f), 10.0f);
    float e = __expf(2.0f * xc);
    return __fdividef(e - 1.0f, e + 1.0f);
}

// ---------- paired dense layer: weights from __constant__ (uniform path) ----------
template<int IN, int OUT, int OUTP, bool ACT>
__device__ __forceinline__ void dense2p(const float* __restrict__ x0, const float* __restrict__ x1,
                                        float* __restrict__ y0, float* __restrict__ y1,
                                        const int WOFF, const int BOFF) {
    constexpr int P = OUTP / 2;
    ull a0[P], a1[P];
#pragma unroll
    for (int j = 0; j < P; j++) {
        ull bv = reinterpret_cast<const ull*>(cW + BOFF)[j];
        a0[j] = bv; a1[j] = bv;
    }
#pragma unroll 4
    for (int i = 0; i < IN; i++) {
        ull xp0 = pack2(x0[i]);
        ull xp1 = pack2(x1[i]);
        const ulonglong2* Wr = reinterpret_cast<const ulonglong2*>(cW + WOFF + i * OUTP);
#pragma unroll
        for (int j = 0; j < P / 2; j++) {
            ulonglong2 w = Wr[j];
            a0[2*j]   = fma2(xp0, w.x, a0[2*j]);
            a0[2*j+1] = fma2(xp0, w.y, a0[2*j+1]);
            a1[2*j]   = fma2(xp1, w.x, a1[2*j]);
            a1[2*j+1] = fma2(xp1, w.y, a1[2*j+1]);
        }
    }
#pragma unroll
    for (int j = 0; j < P; j++) {
        float lo, hi;
        unpack2(lo, hi, a0[j]); y0[2*j] = lo; y0[2*j+1] = hi;
        unpack2(lo, hi, a1[j]); y1[2*j] = lo; y1[2*j+1] = hi;
    }
    if (ACT) {
#pragma unroll
        for (int j = 0; j < OUT; j++) { y0[j] = tanh_fast(y0[j]); y1[j] = tanh_fast(y1[j]); }
    }
}

// ---------- prep: zero stats + build padded/fused weight image (multi-block) ----------
__device__ __forceinline__ void padcpy(int off, const float* __restrict__ src,
                                       int IN, int OUT, int OUTP, int gt, int gn) {
    for (int idx = gt; idx < IN * OUTP; idx += gn) {
        int i = idx / OUTP, j = idx - i * OUTP;
        g_wpad[off + idx] = (j < OUT) ? src[i * OUT + j] : 0.0f;
    }
}
__device__ __forceinline__ void padb(int off, const float* __restrict__ src,
                                     int OUT, int OUTP, int gt) {
    if (gt < OUTP) g_wpad[off + gt] = (gt < OUT) ? src[gt] : 0.0f;
}

__global__ void prep(Params p) {
    int gt = blockIdx.x * blockDim.x + threadIdx.x;
    int gn = gridDim.x * blockDim.x;
    if (gt < 152) g_stats[gt] = 0.0f;
    padcpy(OW1,  p.w[0], 120, 60, 60, gt, gn);
    padcpy(OW2,  p.w[1],  60, 30, 32, gt, gn);
    padcpy(OW3,  p.w[2],  30, 10, 12, gt, gn);
    padcpy(OW4,  p.w[3],  10,  4,  4, gt, gn);
    padcpy(OW5,  p.w[4],   4, 10, 12, gt, gn);
    padcpy(OW6,  p.w[5],  10, 30, 32, gt, gn);
    padcpy(OW7,  p.w[6],  30, 60, 60, gt, gn);
    padcpy(OW10, p.w[9],  10, 10, 12, gt, gn);
    for (int idx = gt; idx < 720; idx += gn) {
        int a = idx / 12, j = idx - a * 12;
        float s = 0.0f;
        if (j < 10) {
#pragma unroll 4
            for (int d = 0; d < 120; d++) s += p.w[7][a * 120 + d] * p.w[8][d * 10 + j];
        }
        g_wpad[OW89 + idx] = s;
    }
    if (gt >= 720 && gt < 732) {
        int j = gt - 720;
        float s = 0.0f;
        if (j < 10) {
            for (int d = 0; d < 120; d++) s += p.b[7][d] * p.w[8][d * 10 + j];
            s += p.b[8][j];
        }
        g_wpad[OB89 + j] = s;
    }
    padb(OB1,  p.b[0], 60, 60, gt);
    padb(OB2,  p.b[1], 30, 32, gt);
    padb(OB3,  p.b[2], 10, 12, gt);
    padb(OB4,  p.b[3],  4,  4, gt);
    padb(OB5,  p.b[4], 10, 12, gt);
    padb(OB6,  p.b[5], 30, 32, gt);
    padb(OB7,  p.b[6], 60, 60, gt);
    padb(OB10, p.b[9], 10, 12, gt);
}

__global__ void dummy_k() {}

// ---------- x chunk staging ----------
__device__ __forceinline__ void stage_x(float* __restrict__ dst, const float* __restrict__ x_in,
                                        int base, int rows, int kc, int tid) {
    for (int idx = tid; idx < rows * 2; idx += TPB) {
        int r = idx >> 1, h = (idx & 1) << 2;
        const float4 v = *reinterpret_cast<const float4*>(x_in + (size_t)(base + r) * 120 + kc * 8 + h);
        float* d = dst + r * XST + h;
        d[0] = v.x; d[1] = v.y; d[2] = v.z; d[3] = v.w;
    }
}

__device__ __forceinline__ void finish_softmax(const float* __restrict__ g,
                                               float* __restrict__ gamma_out, int n) {
    float m = g[0];
#pragma unroll
    for (int j = 1; j < 10; j++) m = fmaxf(m, g[j]);
    float e[10], s = 0.f;
#pragma unroll
    for (int j = 0; j < 10; j++) { e[j] = __expf(g[j] - m); s += e[j]; }
    float inv = __fdividef(1.0f, s);
    float2* gp = reinterpret_cast<float2*>(gamma_out + (size_t)n * 10);
#pragma unroll
    for (int t = 0; t < 5; t++) gp[t] = make_float2(e[2*t] * inv, e[2*t+1] * inv);
}

// ---------- phase 1: persistent paired MLP forward, const weights ----------
__global__ __launch_bounds__(TPB, 1)
void phase1(const float* __restrict__ x_in,
            float* __restrict__ gamma_out, float* __restrict__ zc_out,
            int N, int nChunks) {
    extern __shared__ float sm[];
    float* sX0 = sm;
    float* sX1 = sm + XBUF;
    int tid = threadIdx.x;

#pragma unroll 1
    for (int chunk = blockIdx.x; chunk < nChunks; chunk += GRID1) {
        int base = chunk * CH;
        int rows = N - base; if (rows > CH) rows = CH;

        stage_x(sX0, x_in, base, rows, 0, tid);
        __syncthreads();

        ull acc0[30], acc1[30];
#pragma unroll
        for (int j = 0; j < 30; j++) {
            ull bv = reinterpret_cast<const ull*>(cW + OB1)[j];
            acc0[j] = bv; acc1[j] = bv;
        }

        // L1: 120->60 over 15 k-chunks of 8, double-buffered staging
#pragma unroll 1
        for (int kc = 0; kc < 15; kc++) {
            const float* cur = (kc & 1) ? sX1 : sX0;
            if (kc < 14) stage_x((kc & 1) ? sX0 : sX1, x_in, base, rows, kc + 1, tid);
            const float* xa = cur + tid * XST;
            const float* xb = cur + (tid + 256) * XST;
#pragma unroll
            for (int i = 0; i < 8; i++) {
                ull xp0 = pack2(xa[i]);
                ull xp1 = pack2(xb[i]);
                const ulonglong2* Wr = reinterpret_cast<const ulonglong2*>(cW + OW1 + (kc * 8 + i) * 60);
#pragma unroll
                for (int j = 0; j < 15; j++) {
                    ulonglong2 w = Wr[j];
                    acc0[2*j]   = fma2(xp0, w.x, acc0[2*j]);
                    acc0[2*j+1] = fma2(xp0, w.y, acc0[2*j+1]);
                    acc1[2*j]   = fma2(xp1, w.x, acc1[2*j]);
                    acc1[2*j+1] = fma2(xp1, w.y, acc1[2*j+1]);
                }
            }
            __syncthreads();
        }

        int n0 = base + tid;
        int n1 = base + 256 + tid;
        bool act0 = (n0 < N) && (tid < rows);
        bool act1 = (n1 < N);

        float A0[60], A1[60], B0[60], B1[60];
#pragma unroll
        for (int j = 0; j < 30; j++) {
            float lo, hi;
            unpack2(lo, hi, acc0[j]); A0[2*j] = lo; A0[2*j+1] = hi;
            unpack2(lo, hi, acc1[j]); A1[2*j] = lo; A1[2*j+1] = hi;
        }
#pragma unroll
        for (int j = 0; j < 60; j++) { A0[j] = tanh_fast(A0[j]); A1[j] = tanh_fast(A1[j]); }

        dense2p<60,30,32,true>(A0, A1, B0, B1, OW2, OB2);   // L2
        dense2p<30,10,12,true>(B0, B1, A0, A1, OW3, OB3);   // L3
        float zc0[4], zc1[4];
        dense2p<10,4,4,false>(A0, A1, zc0, zc1, OW4, OB4);  // L4 (latent)
        if (act0) reinterpret_cast<float4*>(zc_out)[n0] = make_float4(zc0[0], zc0[1], zc0[2], zc0[3]);
        if (act1) reinterpret_cast<float4*>(zc_out)[n1] = make_float4(zc1[0], zc1[1], zc1[2], zc1[3]);

        dense2p<4,10,12,true>(zc0, zc1, B0, B1, OW5, OB5);  // L5
        dense2p<10,30,32,true>(B0, B1, A0, A1, OW6, OB6);   // L6
        dense2p<30,60,60,true>(A0, A1, B0, B1, OW7, OB7);   // L7
        float z90[12], z91[12];
        dense2p<60,10,12,true>(B0, B1, z90, z91, OW89, OB89); // fused L8+L9
        float g0[12], g1[12];
        dense2p<10,10,12,false>(z90, z91, g0, g1, OW10, OB10);

        if (act0) finish_softmax(g0, gamma_out, n0);
        if (act1) finish_softmax(g1, gamma_out, n1);
    }
}

// ---------- phase 2: moment reduction ----------
__global__ __launch_bounds__(256, 1)
void phase2(const float* __restrict__ gamma, const float* __restrict__ zc, int N) {
    float acc[150];
#pragma unroll
    for (int v = 0; v < 150; v++) acc[v] = 0.0f;

    int stride = gridDim.x * blockDim.x;
    for (int n = blockIdx.x * blockDim.x + threadIdx.x; n < N; n += stride) {
        float g[10];
        const float2* gp = reinterpret_cast<const float2*>(gamma + (size_t)n * 10);
#pragma unroll
        for (int t = 0; t < 5; t++) { float2 v = gp[t]; g[2*t] = v.x; g[2*t+1] = v.y; }
        float4 z4 = reinterpret_cast<const float4*>(zc)[n];
        float zv[4] = {z4.x, z4.y, z4.z, z4.w};
        float zz[10];
        {
            int t = 0;
#pragma unroll
            for (int d = 0; d < 4; d++)
#pragma unroll
                for (int e = d; e < 4; e++) zz[t++] = zv[d] * zv[e];
        }
#pragma unroll
        for (int k = 0; k < 10; k++) {
            float gk = g[k];
            acc[k] += gk;
#pragma unroll
            for (int d = 0; d < 4; d++) acc[10 + k*4 + d] += gk * zv[d];
#pragma unroll
            for (int t = 0; t < 10; t++) acc[50 + k*10 + t] += gk * zz[t];
        }
    }
#pragma unroll
    for (int v = 0; v < 150; v++) {
        float x = acc[v];
        x += __shfl_xor_sync(0xffffffffu, x, 16);
        x += __shfl_xor_sync(0xffffffffu, x, 8);
        x += __shfl_xor_sync(0xffffffffu, x, 4);
        x += __shfl_xor_sync(0xffffffffu, x, 2);
        x += __shfl_xor_sync(0xffffffffu, x, 1);
        acc[v] = x;
    }
    if ((threadIdx.x & 31) == 0) {
#pragma unroll
        for (int v = 0; v < 150; v++) atomicAdd(&g_stats[v], acc[v]);
    }
}

// ---------- phase 3: GMM params, Cholesky, precision ----------
__global__ void phase3(float* __restrict__ cov_out, float invN) {
    int k = threadIdx.x;
    if (k >= 10) return;
    float sg = g_stats[k];
    float isg = 1.0f / sg;
    float mu[4];
#pragma unroll
    for (int d = 0; d < 4; d++) mu[d] = g_stats[10 + 4*k + d] * isg;
    float C[4][4];
    {
        int t = 0;
#pragma unroll
        for (int d = 0; d < 4; d++)
#pragma unroll
            for (int e = d; e < 4; e++) {
                float c = g_stats[50 + 10*k + t] * isg - mu[d] * mu[e];
                C[d][e] = c; C[e][d] = c; t++;
            }
    }
#pragma unroll
    for (int d = 0; d < 4; d++)
#pragma unroll
        for (int e = 0; e < 4; e++) cov_out[k*16 + d*4 + e] = C[d][e];

#pragma unroll
    for (int d = 0; d < 4; d++) C[d][d] += 1e-6f;

    float L00 = sqrtf(C[0][0]);
    float L10 = C[1][0] / L00, L20 = C[2][0] / L00, L30 = C[3][0] / L00;
    float L11 = sqrtf(C[1][1] - L10*L10);
    float L21 = (C[2][1] - L20*L10) / L11;
    float L31 = (C[3][1] - L30*L10) / L11;
    float L22 = sqrtf(C[2][2] - L20*L20 - L21*L21);
    float L32 = (C[3][2] - L30*L20 - L31*L21) / L22;
    float L33 = sqrtf(C[3][3] - L30*L30 - L31*L31 - L32*L32);
    float logdet = 2.0f * (logf(L00) + logf(L11) + logf(L22) + logf(L33));

    float M00 = 1.0f/L00, M11 = 1.0f/L11, M22 = 1.0f/L22, M33 = 1.0f/L33;
    float M10 = -L10 * M00 * M11;
    float M20 = -(L20*M00 + L21*M10) * M22;
    float M21 = -L21 * M11 * M22;
    float M30 = -(L30*M00 + L31*M10 + L32*M20) * M33;
    float M31 = -(L31*M11 + L32*M21) * M33;
    float M32 = -L32 * M22 * M33;

    float P[4][4];
    P[0][0] = M00*M00 + M10*M10 + M20*M20 + M30*M30;
    P[0][1] = M10*M11 + M20*M21 + M30*M31;
    P[0][2] = M20*M22 + M30*M32;
    P[0][3] = M30*M33;
    P[1][1] = M11*M11 + M21*M21 + M31*M31;
    P[1][2] = M21*M22 + M31*M32;
    P[1][3] = M31*M33;
    P[2][2] = M22*M22 + M32*M32;
    P[2][3] = M32*M33;
    P[3][3] = M33*M33;
    P[1][0] = P[0][1]; P[2][0] = P[0][2]; P[3][0] = P[0][3];
    P[2][1] = P[1][2]; P[3][1] = P[1][3]; P[3][2] = P[2][3];

    float phi = sg * invN;
    const float LOG2PI = 1.8378770664093453f;
    float ck = logf(phi) - 0.5f * (logdet + 4.0f * LOG2PI);

    float* o = g_gmm + k * 21;
#pragma unroll
    for (int d = 0; d < 4; d++) o[d] = mu[d];
#pragma unroll
    for (int d = 0; d < 4; d++)
#pragma unroll
        for (int e = 0; e < 4; e++) o[4 + d*4 + e] = P[d][e];
    o[20] = ck;
}

// ---------- phase 4: per-sample energy ----------
__global__ __launch_bounds__(256)
void phase4(const float* __restrict__ zc, float* __restrict__ energy, int N) {
    __shared__ float sp[212];
    if (threadIdx.x < 212) sp[threadIdx.x] = g_gmm[threadIdx.x];
    __syncthreads();
    int n = blockIdx.x * blockDim.x + threadIdx.x;
    if (n >= N) return;
    float4 z = reinterpret_cast<const float4*>(zc)[n];
    float lp[10];
    float m = -1e30f;
#pragma unroll
    for (int k = 0; k < 10; k++) {
        const float* o = sp + k * 21;
        float d0 = z.x - o[0], d1 = z.y - o[1], d2 = z.z - o[2], d3 = z.w - o[3];
        const float* P = o + 4;
        float q = d0 * (P[0]*d0  + P[1]*d1  + P[2]*d2  + P[3]*d3)
                + d1 * (P[4]*d0  + P[5]*d1  + P[6]*d2  + P[7]*d3)
                + d2 * (P[8]*d0  + P[9]*d1  + P[10]*d2 + P[11]*d3)
                + d3 * (P[12]*d0 + P[13]*d1 + P[14]*d2 + P[15]*d3);
        lp[k] = o[20] - 0.5f * q;
        m = fmaxf(m, lp[k]);
    }
    float s = 0.f;
#pragma unroll
    for (int k = 0; k < 10; k++) s += __expf(lp[k] - m);
    energy[n] = -(m + __logf(s));
}

// ---------- launcher ----------
extern "C" void kernel_launch(void* const* d_in, const int* in_sizes, int n_in,
                              void* d_out, int out_size) {
    const float* x = (const float*)d_in[0];
    Params p;
    for (int i = 0; i < 10; i++) {
        p.w[i] = (const float*)d_in[1 + 2*i];
        p.b[i] = (const float*)d_in[2 + 2*i];
    }
    int N = in_sizes[0] / 120;
    int nChunks = (N + CH - 1) / CH;

    float* out    = (float*)d_out;
    float* energy = out;                       // [N]
    float* gamma  = out + N;                   // [N,10]
    float* zcbuf  = out + (size_t)11 * N;      // [N,4]
    float* covbuf = out + (size_t)15 * N;      // [10,4,4]

    cudaFuncSetAttribute(phase1, cudaFuncAttributeMaxDynamicSharedMemorySize, SMEM_BYTES);

    prep<<<8, 256>>>(p);
    // device->constant copy of the padded/fused weight image (capturable memcpy)
    void* wsrc = nullptr;
    cudaGetSymbolAddress(&wsrc, g_wpad);
    cudaMemcpyToSymbolAsync(cW, wsrc, WTOTAL * sizeof(float), 0,
                            cudaMemcpyDeviceToDevice, 0);
    dummy_k<<<1, 32>>>();   // keep phase1 on the profiler's capture slot
    dummy_k<<<1, 32>>>();
    phase1<<<GRID1, TPB, SMEM_BYTES>>>(x, gamma, zcbuf, N, nChunks);
    phase2<<<148, 256>>>(gamma, zcbuf, N);
    phase3<<<1, 32>>>(covbuf, 1.0f / (float)N);
    phase4<<<(N + 255) / 256, 256>>>(zcbuf, energy, N);
}

// round 7
// speedup vs baseline: 2.1590x; 2.1590x over previous
#include <cuda_runtime.h>
#include <math.h>

typedef unsigned long long ull;

#define TPB 256
#define GRID1 148      // persistent, 1 CTA/SM
#define CH 512         // samples per chunk (2 per thread)
#define XST 9          // staged x row stride (conflict-free scalar LDS)
#define XBUF (CH*XST)  // 4608 floats per buffer

// ---- smem weight layout (float offsets); OUT padded to %4==0 ----
#define OW1  0      // 120x60
#define OW2  7200   // 60x32 (30 real)
#define OW3  9120   // 30x12 (10 real)
#define OW4  9480   // 10x4
#define OW5  9520   // 4x12 (10 real)
#define OW6  9568   // 10x30 (32 pad)
#define OW7  9888   // 30x60
#define OW89 11688  // fused (W8@W9): 60x12 (10 real)
#define OW10 12408  // 10x12 (10 real)
#define OB1  12528
#define OB2  12588
#define OB3  12620
#define OB4  12632
#define OB5  12636
#define OB6  12648
#define OB7  12680
#define OB89 12740
#define OB10 12752
#define WTOTAL 12764
#define SMEM_FLOATS (WTOTAL + 2*XBUF)
#define SMEM_BYTES  (SMEM_FLOATS*4)   // 87,920 B

struct Params { const float* w[10]; const float* b[10]; };

__device__ float g_stats[152];
__device__ float g_wpad[WTOTAL];

// ---------- packed f32x2 helpers ----------
__device__ __forceinline__ ull fma2(ull a, ull b, ull c) {
    ull d; asm("fma.rn.f32x2 %0, %1, %2, %3;" : "=l"(d) : "l"(a), "l"(b), "l"(c)); return d;
}
__device__ __forceinline__ ull pack2(float x) {
    ull r; asm("mov.b64 %0, {%1, %1};" : "=l"(r) : "f"(x)); return r;
}
__device__ __forceinline__ void unpack2(float& lo, float& hi, ull v) {
    asm("mov.b64 {%0, %1}, %2;" : "=f"(lo), "=f"(hi) : "l"(v));
}
__device__ __forceinline__ float tanh_fast(float x) {
    float xc = fminf(fmaxf(x, -10.0f), 10.0f);
    float e = __expf(2.0f * xc);
    return __fdividef(e - 1.0f, e + 1.0f);
}

// ---------- paired dense layer: one weight load serves 2 samples ----------
template<int IN, int OUT, int OUTP, bool ACT>
__device__ __forceinline__ void dense2p(const float* __restrict__ x0, const float* __restrict__ x1,
                                        float* __restrict__ y0, float* __restrict__ y1,
                                        const float* __restrict__ W, const float* __restrict__ b) {
    constexpr int P = OUTP / 2;
    ull a0[P], a1[P];
#pragma unroll
    for (int j = 0; j < P; j++) { ull bv = reinterpret_cast<const ull*>(b)[j]; a0[j] = bv; a1[j] = bv; }
#pragma unroll 4
    for (int i = 0; i < IN; i++) {
        ull xp0 = pack2(x0[i]);
        ull xp1 = pack2(x1[i]);
        const ulonglong2* Wr = reinterpret_cast<const ulonglong2*>(W + i * OUTP);
#pragma unroll
        for (int j = 0; j < P / 2; j++) {
            ulonglong2 w = Wr[j];
            a0[2*j]   = fma2(xp0, w.x, a0[2*j]);
            a0[2*j+1] = fma2(xp0, w.y, a0[2*j+1]);
            a1[2*j]   = fma2(xp1, w.x, a1[2*j]);
            a1[2*j+1] = fma2(xp1, w.y, a1[2*j+1]);
        }
    }
#pragma unroll
    for (int j = 0; j < P; j++) {
        float lo, hi;
        unpack2(lo, hi, a0[j]); y0[2*j] = lo; y0[2*j+1] = hi;
        unpack2(lo, hi, a1[j]); y1[2*j] = lo; y1[2*j+1] = hi;
    }
    if (ACT) {
#pragma unroll
        for (int j = 0; j < OUT; j++) { y0[j] = tanh_fast(y0[j]); y1[j] = tanh_fast(y1[j]); }
    }
}

// ---------- prep: zero stats + build padded/fused weight image ----------
__device__ __forceinline__ void padcpy(int off, const float* __restrict__ src,
                                       int IN, int OUT, int OUTP, int gt, int gn) {
    for (int idx = gt; idx < IN * OUTP; idx += gn) {
        int i = idx / OUTP, j = idx - i * OUTP;
        g_wpad[off + idx] = (j < OUT) ? src[i * OUT + j] : 0.0f;
    }
}
__device__ __forceinline__ void padb(int off, const float* __restrict__ src,
                                     int OUT, int OUTP, int gt) {
    if (gt < OUTP) g_wpad[off + gt] = (gt < OUT) ? src[gt] : 0.0f;
}

__global__ void prep(Params p) {
    int gt = blockIdx.x * blockDim.x + threadIdx.x;
    int gn = gridDim.x * blockDim.x;
    if (gt < 152) g_stats[gt] = 0.0f;
    padcpy(OW1,  p.w[0], 120, 60, 60, gt, gn);
    padcpy(OW2,  p.w[1],  60, 30, 32, gt, gn);
    padcpy(OW3,  p.w[2],  30, 10, 12, gt, gn);
    padcpy(OW4,  p.w[3],  10,  4,  4, gt, gn);
    padcpy(OW5,  p.w[4],   4, 10, 12, gt, gn);
    padcpy(OW6,  p.w[5],  10, 30, 32, gt, gn);
    padcpy(OW7,  p.w[6],  30, 60, 60, gt, gn);
    padcpy(OW10, p.w[9],  10, 10, 12, gt, gn);
    for (int idx = gt; idx < 720; idx += gn) {
        int a = idx / 12, j = idx - a * 12;
        float s = 0.0f;
        if (j < 10) {
#pragma unroll 4
            for (int d = 0; d < 120; d++) s += p.w[7][a * 120 + d] * p.w[8][d * 10 + j];
        }
        g_wpad[OW89 + idx] = s;
    }
    if (gt >= 720 && gt < 732) {
        int j = gt - 720;
        float s = 0.0f;
        if (j < 10) {
            for (int d = 0; d < 120; d++) s += p.b[7][d] * p.w[8][d * 10 + j];
            s += p.b[8][j];
        }
        g_wpad[OB89 + j] = s;
    }
    padb(OB1,  p.b[0], 60, 60, gt);
    padb(OB2,  p.b[1], 30, 32, gt);
    padb(OB3,  p.b[2], 10, 12, gt);
    padb(OB4,  p.b[3],  4,  4, gt);
    padb(OB5,  p.b[4], 10, 12, gt);
    padb(OB6,  p.b[5], 30, 32, gt);
    padb(OB7,  p.b[6], 60, 60, gt);
    padb(OB10, p.b[9], 10, 12, gt);
}

__global__ void dummy_k() {}

// ---------- x chunk staging ----------
__device__ __forceinline__ void stage_x(float* __restrict__ dst, const float* __restrict__ x_in,
                                        int base, int rows, int kc, int tid) {
    for (int idx = tid; idx < rows * 2; idx += TPB) {
        int r = idx >> 1, h = (idx & 1) << 2;
        const float4 v = *reinterpret_cast<const float4*>(x_in + (size_t)(base + r) * 120 + kc * 8 + h);
        float* d = dst + r * XST + h;
        d[0] = v.x; d[1] = v.y; d[2] = v.z; d[3] = v.w;
    }
}

__device__ __forceinline__ void finish_softmax(const float* __restrict__ g,
                                               float* __restrict__ gamma_out, int n) {
    float m = g[0];
#pragma unroll
    for (int j = 1; j < 10; j++) m = fmaxf(m, g[j]);
    float e[10], s = 0.f;
#pragma unroll
    for (int j = 0; j < 10; j++) { e[j] = __expf(g[j] - m); s += e[j]; }
    float inv = __fdividef(1.0f, s);
    float2* gp = reinterpret_cast<float2*>(gamma_out + (size_t)n * 10);
#pragma unroll
    for (int t = 0; t < 5; t++) gp[t] = make_float2(e[2*t] * inv, e[2*t+1] * inv);
}

// ---------- phase 1: persistent paired MLP, balanced contiguous ranges ----------
__global__ __launch_bounds__(TPB, 1)
void phase1(const float* __restrict__ x_in,
            float* __restrict__ gamma_out, float* __restrict__ zc_out, int N) {
    extern __shared__ float sm[];
    float* sW  = sm;
    float* sX0 = sm + WTOTAL;
    float* sX1 = sX0 + XBUF;
    int tid = threadIdx.x;

    // balanced contiguous range for this CTA
    int per = N / GRID1, rem = N - per * GRID1;
    int bid = blockIdx.x;
    int start = bid * per + (bid < rem ? bid : rem);
    int count = per + (bid < rem ? 1 : 0);

    // weights once per CTA
    {
        const float4* src = reinterpret_cast<const float4*>(g_wpad);
        float4* dst = reinterpret_cast<float4*>(sW);
        for (int idx = tid; idx < WTOTAL / 4; idx += TPB) dst[idx] = src[idx];
    }

#pragma unroll 1
    for (int off = 0; off < count; off += CH) {
        int base = start + off;
        int rows = count - off; if (rows > CH) rows = CH;

        stage_x(sX0, x_in, base, rows, 0, tid);
        __syncthreads();   // weights (first iter) + staged chunk

        ull acc0[30], acc1[30];
#pragma unroll
        for (int j = 0; j < 30; j++) {
            ull bv = reinterpret_cast<const ull*>(sW + OB1)[j];
            acc0[j] = bv; acc1[j] = bv;
        }

#pragma unroll 1
        for (int kc = 0; kc < 15; kc++) {
            const float* cur = (kc & 1) ? sX1 : sX0;
            if (kc < 14) stage_x((kc & 1) ? sX0 : sX1, x_in, base, rows, kc + 1, tid);
            const float* xa = cur + tid * XST;
            const float* xb = cur + (tid + 256) * XST;
#pragma unroll
            for (int i = 0; i < 8; i++) {
                ull xp0 = pack2(xa[i]);
                ull xp1 = pack2(xb[i]);
                const ulonglong2* Wr = reinterpret_cast<const ulonglong2*>(sW + OW1 + (kc * 8 + i) * 60);
#pragma unroll
                for (int j = 0; j < 15; j++) {
                    ulonglong2 w = Wr[j];
                    acc0[2*j]   = fma2(xp0, w.x, acc0[2*j]);
                    acc0[2*j+1] = fma2(xp0, w.y, acc0[2*j+1]);
                    acc1[2*j]   = fma2(xp1, w.x, acc1[2*j]);
                    acc1[2*j+1] = fma2(xp1, w.y, acc1[2*j+1]);
                }
            }
            __syncthreads();
        }

        int n0 = base + tid;
        int n1 = base + 256 + tid;
        bool act0 = (tid < rows);
        bool act1 = (tid + 256 < rows);

        float A0[60], A1[60], B0[60], B1[60];
#pragma unroll
        for (int j = 0; j < 30; j++) {
            float lo, hi;
            unpack2(lo, hi, acc0[j]); A0[2*j] = lo; A0[2*j+1] = hi;
            unpack2(lo, hi, acc1[j]); A1[2*j] = lo; A1[2*j+1] = hi;
        }
#pragma unroll
        for (int j = 0; j < 60; j++) { A0[j] = tanh_fast(A0[j]); A1[j] = tanh_fast(A1[j]); }

        dense2p<60,30,32,true>(A0, A1, B0, B1, sW + OW2, sW + OB2);   // L2
        dense2p<30,10,12,true>(B0, B1, A0, A1, sW + OW3, sW + OB3);   // L3
        float zc0[4], zc1[4];
        dense2p<10,4,4,false>(A0, A1, zc0, zc1, sW + OW4, sW + OB4);  // L4 (latent)
        if (act0) reinterpret_cast<float4*>(zc_out)[n0] = make_float4(zc0[0], zc0[1], zc0[2], zc0[3]);
        if (act1) reinterpret_cast<float4*>(zc_out)[n1] = make_float4(zc1[0], zc1[1], zc1[2], zc1[3]);

        dense2p<4,10,12,true>(zc0, zc1, B0, B1, sW + OW5, sW + OB5);  // L5
        dense2p<10,30,32,true>(B0, B1, A0, A1, sW + OW6, sW + OB6);   // L6
        dense2p<30,60,60,true>(A0, A1, B0, B1, sW + OW7, sW + OB7);   // L7
        float z90[12], z91[12];
        dense2p<60,10,12,true>(B0, B1, z90, z91, sW + OW89, sW + OB89); // fused L8+L9
        float g0[12], g1[12];
        dense2p<10,10,12,false>(z90, z91, g0, g1, sW + OW10, sW + OB10);

        if (act0) finish_softmax(g0, gamma_out, n0);
        if (act1) finish_softmax(g1, gamma_out, n1);
    }
}

// ---------- phase 2: moment reduction (smem-staged atomics) ----------
__global__ __launch_bounds__(256, 1)
void phase2(const float* __restrict__ gamma, const float* __restrict__ zc, int N) {
    __shared__ float wsum[8][150];
    float acc[150];
#pragma unroll
    for (int v = 0; v < 150; v++) acc[v] = 0.0f;

    int stride = gridDim.x * blockDim.x;
    for (int n = blockIdx.x * blockDim.x + threadIdx.x; n < N; n += stride) {
        float g[10];
        const float2* gp = reinterpret_cast<const float2*>(gamma + (size_t)n * 10);
#pragma unroll
        for (int t = 0; t < 5; t++) { float2 v = gp[t]; g[2*t] = v.x; g[2*t+1] = v.y; }
        float4 z4 = reinterpret_cast<const float4*>(zc)[n];
        float zv[4] = {z4.x, z4.y, z4.z, z4.w};
        float zz[10];
        {
            int t = 0;
#pragma unroll
            for (int d = 0; d < 4; d++)
#pragma unroll
                for (int e = d; e < 4; e++) zz[t++] = zv[d] * zv[e];
        }
#pragma unroll
        for (int k = 0; k < 10; k++) {
            float gk = g[k];
            acc[k] += gk;
#pragma unroll
            for (int d = 0; d < 4; d++) acc[10 + k*4 + d] += gk * zv[d];
#pragma unroll
            for (int t = 0; t < 10; t++) acc[50 + k*10 + t] += gk * zz[t];
        }
    }
#pragma unroll
    for (int v = 0; v < 150; v++) {
        float x = acc[v];
        x += __shfl_xor_sync(0xffffffffu, x, 16);
        x += __shfl_xor_sync(0xffffffffu, x, 8);
        x += __shfl_xor_sync(0xffffffffu, x, 4);
        x += __shfl_xor_sync(0xffffffffu, x, 2);
        x += __shfl_xor_sync(0xffffffffu, x, 1);
        acc[v] = x;
    }
    int wid = threadIdx.x >> 5;
    if ((threadIdx.x & 31) == 0) {
#pragma unroll
        for (int v = 0; v < 150; v++) wsum[wid][v] = acc[v];
    }
    __syncthreads();
    if (threadIdx.x < 150) {
        float s = 0.f;
#pragma unroll
        for (int w = 0; w < 8; w++) s += wsum[w][threadIdx.x];
        atomicAdd(&g_stats[threadIdx.x], s);
    }
}

// ---------- phase 3+4 fused: GMM params (redundant per block) + energy ----------
__global__ __launch_bounds__(256)
void phase34(const float* __restrict__ zc, float* __restrict__ energy,
             float* __restrict__ cov_out, float invN, int N) {
    __shared__ float sp[212];   // per k (stride 21): mu[4], P[16], logconst
    int k = threadIdx.x;
    if (k < 10) {
        float sg = g_stats[k];
        float isg = 1.0f / sg;
        float mu[4];
#pragma unroll
        for (int d = 0; d < 4; d++) mu[d] = g_stats[10 + 4*k + d] * isg;
        float C[4][4];
        {
            int t = 0;
#pragma unroll
            for (int d = 0; d < 4; d++)
#pragma unroll
                for (int e = d; e < 4; e++) {
                    float c = g_stats[50 + 10*k + t] * isg - mu[d] * mu[e];
                    C[d][e] = c; C[e][d] = c; t++;
                }
        }
        if (blockIdx.x == 0) {
#pragma unroll
            for (int d = 0; d < 4; d++)
#pragma unroll
                for (int e = 0; e < 4; e++) cov_out[k*16 + d*4 + e] = C[d][e];
        }
#pragma unroll
        for (int d = 0; d < 4; d++) C[d][d] += 1e-6f;

        float L00 = sqrtf(C[0][0]);
        float L10 = C[1][0] / L00, L20 = C[2][0] / L00, L30 = C[3][0] / L00;
        float L11 = sqrtf(C[1][1] - L10*L10);
        float L21 = (C[2][1] - L20*L10) / L11;
        float L31 = (C[3][1] - L30*L10) / L11;
        float L22 = sqrtf(C[2][2] - L20*L20 - L21*L21);
        float L32 = (C[3][2] - L30*L20 - L31*L21) / L22;
        float L33 = sqrtf(C[3][3] - L30*L30 - L31*L31 - L32*L32);
        float logdet = 2.0f * (logf(L00) + logf(L11) + logf(L22) + logf(L33));

        float M00 = 1.0f/L00, M11 = 1.0f/L11, M22 = 1.0f/L22, M33 = 1.0f/L33;
        float M10 = -L10 * M00 * M11;
        float M20 = -(L20*M00 + L21*M10) * M22;
        float M21 = -L21 * M11 * M22;
        float M30 = -(L30*M00 + L31*M10 + L32*M20) * M33;
        float M31 = -(L31*M11 + L32*M21) * M33;
        float M32 = -L32 * M22 * M33;

        float P[4][4];
        P[0][0] = M00*M00 + M10*M10 + M20*M20 + M30*M30;
        P[0][1] = M10*M11 + M20*M21 + M30*M31;
        P[0][2] = M20*M22 + M30*M32;
        P[0][3] = M30*M33;
        P[1][1] = M11*M11 + M21*M21 + M31*M31;
        P[1][2] = M21*M22 + M31*M32;
        P[1][3] = M31*M33;
        P[2][2] = M22*M22 + M32*M32;
        P[2][3] = M32*M33;
        P[3][3] = M33*M33;
        P[1][0] = P[0][1]; P[2][0] = P[0][2]; P[3][0] = P[0][3];
        P[2][1] = P[1][2]; P[3][1] = P[1][3]; P[3][2] = P[2][3];

        float phi = sg * invN;
        const float LOG2PI = 1.8378770664093453f;
        float ck = logf(phi) - 0.5f * (logdet + 4.0f * LOG2PI);

        float* o = sp + k * 21;
#pragma unroll
        for (int d = 0; d < 4; d++) o[d] = mu[d];
#pragma unroll
        for (int d = 0; d < 4; d++)
#pragma unroll
            for (int e = 0; e < 4; e++) o[4 + d*4 + e] = P[d][e];
        o[20] = ck;
    }
    __syncthreads();

    int n = blockIdx.x * blockDim.x + threadIdx.x;
    if (n >= N) return;
    float4 z = reinterpret_cast<const float4*>(zc)[n];
    float lp[10];
    float m = -1e30f;
#pragma unroll
    for (int kk = 0; kk < 10; kk++) {
        const float* o = sp + kk * 21;
        float d0 = z.x - o[0], d1 = z.y - o[1], d2 = z.z - o[2], d3 = z.w - o[3];
        const float* P = o + 4;
        float q = d0 * (P[0]*d0  + P[1]*d1  + P[2]*d2  + P[3]*d3)
                + d1 * (P[4]*d0  + P[5]*d1  + P[6]*d2  + P[7]*d3)
                + d2 * (P[8]*d0  + P[9]*d1  + P[10]*d2 + P[11]*d3)
                + d3 * (P[12]*d0 + P[13]*d1 + P[14]*d2 + P[15]*d3);
        lp[kk] = o[20] - 0.5f * q;
        m = fmaxf(m, lp[kk]);
    }
    float s = 0.f;
#pragma unroll
    for (int kk = 0; kk < 10; kk++) s += __expf(lp[kk] - m);
    energy[n] = -(m + __logf(s));
}

// ---------- launcher ----------
extern "C" void kernel_launch(void* const* d_in, const int* in_sizes, int n_in,
                              void* d_out, int out_size) {
    const float* x = (const float*)d_in[0];
    Params p;
    for (int i = 0; i < 10; i++) {
        p.w[i] = (const float*)d_in[1 + 2*i];
        p.b[i] = (const float*)d_in[2 + 2*i];
    }
    int N = in_sizes[0] / 120;

    float* out    = (float*)d_out;
    float* energy = out;                       // [N]
    float* gamma  = out + N;                   // [N,10]
    float* zcbuf  = out + (size_t)11 * N;      // [N,4]
    float* covbuf = out + (size_t)15 * N;      // [10,4,4]

    cudaFuncSetAttribute(phase1, cudaFuncAttributeMaxDynamicSharedMemorySize, SMEM_BYTES);

    prep<<<8, 256>>>(p);
    dummy_k<<<1, 32>>>();
    phase1<<<GRID1, TPB, SMEM_BYTES>>>(x, gamma, zcbuf, N);
    phase2<<<148, 256>>>(gamma, zcbuf, N);     // index 3: profiled next round
    phase34<<<(N + 255) / 256, 256>>>(zcbuf, energy, covbuf, 1.0f / (float)N, N);
}